// round 13
// baseline (speedup 1.0000x reference)
#include <cuda_runtime.h>
#include <cuda_bf16.h>
#include <cstdint>

constexpr int B_  = 4;
constexpr int S_  = 2048;
constexpr int C_  = 1024;
constexpr int H_  = 16;
constexpr int HS_ = 64;
constexpr int M_  = B_ * S_;                    // 8192
constexpr int QKV_ELEMS = B_ * H_ * S_ * HS_;   // 8388608
constexpr int KP_ = C_ / 2;                     // 512 packed k-pairs

__device__ float g_v[QKV_ELEMS];                    // V fp32 [B,H,S,HS] (pack_v input)
__device__ uint32_t g_whi[3 * C_ * KP_];            // [mat][n][kp] packed bf16 pairs
__device__ uint32_t g_wlo[3 * C_ * KP_];
__device__ uint32_t g_phi[C_ * KP_];                // [n][kp] for Wp^T
__device__ uint32_t g_plo[C_ * KP_];

// activation hi/lo planes (packed bf16 pairs)
__device__ uint32_t x_hi[M_ * KP_];                 // [m][kp]
__device__ uint32_t x_lo[M_ * KP_];
__device__ uint32_t o_hi[M_ * KP_];                 // [m][kp], kp = h*32 + d/2
__device__ uint32_t o_lo[M_ * KP_];
__device__ uint32_t q_hi[QKV_ELEMS / 2];            // [bh][s][dp] (scaled 0.125)
__device__ uint32_t q_lo[QKV_ELEMS / 2];
__device__ uint32_t k_hi[QKV_ELEMS / 2];
__device__ uint32_t k_lo[QKV_ELEMS / 2];
__device__ uint32_t v_hi[QKV_ELEMS / 2];            // [bh][d][tp] (pairs over t)
__device__ uint32_t v_lo[QKV_ELEMS / 2];

// ---------------------------------------------------------------------------
__device__ __forceinline__ uint32_t pack2(__nv_bfloat16 a, __nv_bfloat16 b) {
    __nv_bfloat162 t; t.x = a; t.y = b;
    return *reinterpret_cast<uint32_t*>(&t);
}
__device__ __forceinline__ void decomp2(float a, float b, uint32_t& hi, uint32_t& lo) {
    __nv_bfloat16 ha = __float2bfloat16(a);
    __nv_bfloat16 hb = __float2bfloat16(b);
    __nv_bfloat16 la = __float2bfloat16(a - __bfloat162float(ha));
    __nv_bfloat16 lb = __float2bfloat16(b - __bfloat162float(hb));
    hi = pack2(ha, hb);
    lo = pack2(la, lb);
}

__device__ __forceinline__ void mma_bf16(float* d, const uint32_t* a, const uint32_t* b) {
    asm volatile(
        "mma.sync.aligned.m16n8k16.row.col.f32.bf16.bf16.f32 "
        "{%0,%1,%2,%3}, {%4,%5,%6,%7}, {%8,%9}, {%0,%1,%2,%3};\n"
        : "+f"(d[0]), "+f"(d[1]), "+f"(d[2]), "+f"(d[3])
        : "r"(a[0]), "r"(a[1]), "r"(a[2]), "r"(a[3]), "r"(b[0]), "r"(b[1]));
}

// ldmatrix x4: 4 m8n8 b16 matrices; lanes 0-7/8-15/16-23/24-31 give row addrs.
__device__ __forceinline__ void ldsm_x4(uint32_t& r0, uint32_t& r1,
                                        uint32_t& r2, uint32_t& r3, uint32_t saddr) {
    asm volatile("ldmatrix.sync.aligned.m8n8.x4.shared.b16 {%0,%1,%2,%3}, [%4];"
                 : "=r"(r0), "=r"(r1), "=r"(r2), "=r"(r3) : "r"(saddr));
}

__device__ __forceinline__ void cp16(void* dst, const void* src) {
    uint32_t d = (uint32_t)__cvta_generic_to_shared(dst);
    asm volatile("cp.async.cg.shared.global [%0], [%1], 16;" :: "r"(d), "l"(src));
}
#define CP_COMMIT asm volatile("cp.async.commit_group;")
#define CP_WAIT0  asm volatile("cp.async.wait_group 0;")
#define CP_WAIT1  asm volatile("cp.async.wait_group 1;")

// ---------------------------------------------------------------------------
// Packs (unchanged)
// ---------------------------------------------------------------------------
__global__ void pack_x_kernel(const float* __restrict__ x) {
    int idx = blockIdx.x * 256 + threadIdx.x;
    int m  = idx >> 9;
    int kp = idx & 511;
    float2 f = *(const float2*)(x + (size_t)m * C_ + 2 * kp);
    uint32_t hi, lo;
    decomp2(f.x, f.y, hi, lo);
    x_hi[idx] = hi;
    x_lo[idx] = lo;
}

__global__ void pack_w_kernel(const float* __restrict__ Wq,
                              const float* __restrict__ Wk,
                              const float* __restrict__ Wv) {
    int idx = blockIdx.x * 256 + threadIdx.x;
    int mat = idx / (C_ * KP_);
    int rem = idx - mat * (C_ * KP_);
    int n   = rem >> 9;
    int kp  = rem & 511;
    const float* W = (mat == 0) ? Wq : (mat == 1) ? Wk : Wv;
    int h = n >> 6, d = n & 63;
    const float* base = W + (size_t)h * C_ * HS_ + (size_t)(2 * kp) * HS_ + d;
    uint32_t hi, lo;
    decomp2(base[0], base[HS_], hi, lo);
    g_whi[idx] = hi;
    g_wlo[idx] = lo;
}

__global__ void pack_wp_kernel(const float* __restrict__ Wp) {
    int idx = blockIdx.x * 256 + threadIdx.x;
    int n  = idx >> 9;
    int kp = idx & 511;
    float2 f = *(const float2*)(Wp + (size_t)n * C_ + 2 * kp);
    uint32_t hi, lo;
    decomp2(f.x, f.y, hi, lo);
    g_phi[idx] = hi;
    g_plo[idx] = lo;
}

__global__ __launch_bounds__(256) void pack_v_kernel() {
    const int bh = blockIdx.y;
    const int t0 = blockIdx.x * 128;
    __shared__ float sm[128][65];
    const int tid = threadIdx.x;

    const float* src = g_v + (size_t)bh * S_ * HS_ + (size_t)t0 * HS_;
    #pragma unroll
    for (int i = 0; i < 8; i++) {
        int lin = i * 256 + tid;
        int row = lin >> 4, c4 = lin & 15;
        float4 v = *(const float4*)(src + (size_t)row * HS_ + c4 * 4);
        sm[row][c4 * 4 + 0] = v.x;
        sm[row][c4 * 4 + 1] = v.y;
        sm[row][c4 * 4 + 2] = v.z;
        sm[row][c4 * 4 + 3] = v.w;
    }
    __syncthreads();

    const size_t obase = (size_t)bh * (HS_ * (S_ / 2)) + (size_t)(t0 >> 1);
    #pragma unroll
    for (int j = 0; j < 16; j++) {
        int d  = (tid >> 6) + j * 4;
        int tp = tid & 63;
        uint32_t hi, lo;
        decomp2(sm[2 * tp][d], sm[2 * tp + 1][d], hi, lo);
        v_hi[obase + (size_t)d * (S_ / 2) + tp] = hi;
        v_lo[obase + (size_t)d * (S_ / 2) + tp] = lo;
    }
}

// ---------------------------------------------------------------------------
// GEMM: K-step 32 per stage, 2-stage double buffer, ldmatrix fragment loads.
// Stride 20 u32/row: ldmatrix 8-row phases hit banks {0,20,8,28,16,4,24,12}.
// ---------------------------------------------------------------------------
constexpr int PSTR = 20;
constexpr int STAGE_U32 = 4 * 128 * PSTR;           // 40960 B
constexpr int GEMM_SMEM = 2 * STAGE_U32 * 4;        // 81920 B

__device__ __forceinline__ void gemm_compute(
    uint32_t sAh, uint32_t sAl, uint32_t sBh, uint32_t sBl,   // smem byte addrs
    int wm, int wn, int lane, float acc[4][4][4])
{
    const int r8 = lane & 7;
    // A x4: groups = (rows0-7,k0-7)(rows8-15,k0-7)(rows0-7,k8-15)(rows8-15,k8-15)
    const int aoff = ((r8 + ((lane >> 3) & 1) * 8) * PSTR + (lane >> 4) * 4) * 4;
    // B x4: groups = (nt rows,k0-7)(nt rows,k8-15)(nt+1 rows,k0-7)(nt+1 rows,k8-15)
    const int boff = ((r8 + (lane >> 4) * 8) * PSTR + ((lane >> 3) & 1) * 4) * 4;

    #pragma unroll
    for (int ks = 0; ks < 2; ks++) {
        const int kc = ks * 8 * 4;      // byte offset of k-block
        uint32_t ah[4][4], al[4][4], bh[4][2], bl[4][2];
        #pragma unroll
        for (int mt = 0; mt < 4; mt++) {
            uint32_t base = (uint32_t)((wm + mt * 16) * PSTR * 4 + kc) + aoff;
            ldsm_x4(ah[mt][0], ah[mt][1], ah[mt][2], ah[mt][3], sAh + base);
            ldsm_x4(al[mt][0], al[mt][1], al[mt][2], al[mt][3], sAl + base);
        }
        #pragma unroll
        for (int np = 0; np < 2; np++) {
            uint32_t base = (uint32_t)((wn + np * 16) * PSTR * 4 + kc) + boff;
            ldsm_x4(bh[2*np][0], bh[2*np][1], bh[2*np+1][0], bh[2*np+1][1], sBh + base);
            ldsm_x4(bl[2*np][0], bl[2*np][1], bl[2*np+1][0], bl[2*np+1][1], sBl + base);
        }
        #pragma unroll
        for (int mt = 0; mt < 4; mt++)
            #pragma unroll
            for (int nt = 0; nt < 4; nt++) {
                mma_bf16(acc[mt][nt], ah[mt], bh[nt]);
                mma_bf16(acc[mt][nt], ah[mt], bl[nt]);
                mma_bf16(acc[mt][nt], al[mt], bh[nt]);
            }
    }
}

// Issue one K32 stage: 2048 cp16 over 256 threads (A hi/lo + B hi/lo).
__device__ __forceinline__ void gemm_issue(
    uint32_t* stage,
    const uint32_t* __restrict__ Ahg, const uint32_t* __restrict__ Alg,
    const uint32_t* __restrict__ Bhg, const uint32_t* __restrict__ Blg,
    int m0, int n0, int kp0, int tid)
{
    #pragma unroll
    for (int i = 0; i < 8; i++) {
        int c     = i * 256 + tid;
        int plane = c >> 9;
        int rem   = c & 511;
        int row   = rem >> 2;
        int ch    = rem & 3;
        const uint32_t* srcb =
            (plane == 0) ? Ahg : (plane == 1) ? Alg : (plane == 2) ? Bhg : Blg;
        int rb = (plane < 2) ? m0 : n0;
        cp16(stage + plane * (128 * PSTR) + row * PSTR + ch * 4,
             srcb + (size_t)(rb + row) * KP_ + kp0 + ch * 4);
    }
    CP_COMMIT;
}

// ---------------------------------------------------------------------------
// QKV GEMM (double-buffered). Epilogue: q/k packed planes (q scaled), v fp32.
// ---------------------------------------------------------------------------
__global__ __launch_bounds__(256, 2) void qkv_gemm() {
    const int mat = blockIdx.z;
    const uint32_t* Whi = g_whi + (size_t)mat * C_ * KP_;
    const uint32_t* Wlo = g_wlo + (size_t)mat * C_ * KP_;

    const int n0 = blockIdx.x * 128;
    const int m0 = blockIdx.y * 128;

    extern __shared__ uint32_t dynsm[];
    uint32_t* stg[2] = {dynsm, dynsm + STAGE_U32};
    const uint32_t sb = (uint32_t)__cvta_generic_to_shared(dynsm);

    const int tid  = threadIdx.x;
    const int warp = tid >> 5;
    const int lane = tid & 31;
    const int gid  = lane >> 2;
    const int tig  = lane & 3;
    const int wm   = (warp & 1) * 64;
    const int wn   = (warp >> 1) * 32;

    float acc[4][4][4];
    #pragma unroll
    for (int mt = 0; mt < 4; mt++)
        #pragma unroll
        for (int nt = 0; nt < 4; nt++)
            #pragma unroll
            for (int e = 0; e < 4; e++) acc[mt][nt][e] = 0.f;

    gemm_issue(stg[0], x_hi, x_lo, Whi, Wlo, m0, n0, 0, tid);

    int st = 0;
    for (int kp0 = 0; kp0 < KP_; kp0 += 16) {
        if (kp0 + 16 < KP_) {
            gemm_issue(stg[st ^ 1], x_hi, x_lo, Whi, Wlo, m0, n0, kp0 + 16, tid);
            CP_WAIT1;
        } else {
            CP_WAIT0;
        }
        __syncthreads();
        uint32_t ss = sb + (uint32_t)(st * STAGE_U32 * 4);
        gemm_compute(ss, ss + 128 * PSTR * 4,
                     ss + 2 * 128 * PSTR * 4, ss + 3 * 128 * PSTR * 4,
                     wm, wn, lane, acc);
        __syncthreads();
        st ^= 1;
    }

    if (mat == 2) {
        #pragma unroll
        for (int mt = 0; mt < 4; mt++) {
            int r  = m0 + wm + mt * 16 + gid;
            int b  = r >> 11;
            int s0 = r & 2047;
            #pragma unroll
            for (int nt = 0; nt < 4; nt++) {
                int n    = n0 + wn + nt * 8 + 2 * tig;
                int head = n >> 6;
                int d    = n & 63;
                float* p0 = g_v + ((size_t)(b * H_ + head) * S_ + s0) * HS_ + d;
                *(float2*)p0             = make_float2(acc[mt][nt][0], acc[mt][nt][1]);
                *(float2*)(p0 + 8 * HS_) = make_float2(acc[mt][nt][2], acc[mt][nt][3]);
            }
        }
    } else {
        const float scale = (mat == 0) ? 0.125f : 1.0f;
        uint32_t* hiP = (mat == 0) ? q_hi : k_hi;
        uint32_t* loP = (mat == 0) ? q_lo : k_lo;
        #pragma unroll
        for (int mt = 0; mt < 4; mt++) {
            int r  = m0 + wm + mt * 16 + gid;
            int b  = r >> 11;
            int s0 = r & 2047;
            #pragma unroll
            for (int nt = 0; nt < 4; nt++) {
                int n    = n0 + wn + nt * 8 + 2 * tig;
                int head = n >> 6;
                int dp   = (n & 63) >> 1;
                size_t i0 = ((size_t)(b * H_ + head) * S_ + s0) * 32 + dp;
                uint32_t hi, lo;
                decomp2(acc[mt][nt][0] * scale, acc[mt][nt][1] * scale, hi, lo);
                hiP[i0] = hi; loP[i0] = lo;
                decomp2(acc[mt][nt][2] * scale, acc[mt][nt][3] * scale, hi, lo);
                hiP[i0 + 8 * 32] = hi; loP[i0 + 8 * 32] = lo;
            }
        }
    }
}

// ---------------------------------------------------------------------------
// Projection GEMM (double-buffered): A = o planes, B = Wp^T planes.
// ---------------------------------------------------------------------------
__global__ __launch_bounds__(256, 2) void proj_gemm(
    const float* __restrict__ bp, float* __restrict__ out)
{
    const int n0 = blockIdx.x * 128;
    const int m0 = blockIdx.y * 128;

    extern __shared__ uint32_t dynsm[];
    uint32_t* stg[2] = {dynsm, dynsm + STAGE_U32};
    const uint32_t sb = (uint32_t)__cvta_generic_to_shared(dynsm);

    const int tid  = threadIdx.x;
    const int warp = tid >> 5;
    const int lane = tid & 31;
    const int gid  = lane >> 2;
    const int tig  = lane & 3;
    const int wm   = (warp & 1) * 64;
    const int wn   = (warp >> 1) * 32;

    float acc[4][4][4];
    #pragma unroll
    for (int mt = 0; mt < 4; mt++)
        #pragma unroll
        for (int nt = 0; nt < 4; nt++)
            #pragma unroll
            for (int e = 0; e < 4; e++) acc[mt][nt][e] = 0.f;

    gemm_issue(stg[0], o_hi, o_lo, g_phi, g_plo, m0, n0, 0, tid);

    int st = 0;
    for (int kp0 = 0; kp0 < KP_; kp0 += 16) {
        if (kp0 + 16 < KP_) {
            gemm_issue(stg[st ^ 1], o_hi, o_lo, g_phi, g_plo, m0, n0, kp0 + 16, tid);
            CP_WAIT1;
        } else {
            CP_WAIT0;
        }
        __syncthreads();
        uint32_t ss = sb + (uint32_t)(st * STAGE_U32 * 4);
        gemm_compute(ss, ss + 128 * PSTR * 4,
                     ss + 2 * 128 * PSTR * 4, ss + 3 * 128 * PSTR * 4,
                     wm, wn, lane, acc);
        __syncthreads();
        st ^= 1;
    }

    #pragma unroll
    for (int mt = 0; mt < 4; mt++) {
        int r = m0 + wm + mt * 16 + gid;
        #pragma unroll
        for (int nt = 0; nt < 4; nt++) {
            int n = n0 + wn + nt * 8 + 2 * tig;
            float2 bias = *(const float2*)(bp + n);
            *(float2*)(out + (size_t)r * C_ + n) =
                make_float2(acc[mt][nt][0] + bias.x, acc[mt][nt][1] + bias.y);
            *(float2*)(out + (size_t)(r + 8) * C_ + n) =
                make_float2(acc[mt][nt][2] + bias.x, acc[mt][nt][3] + bias.y);
        }
    }
}

// ---------------------------------------------------------------------------
// Flash attention: ldmatrix fragment loads for K and V (numerics unchanged).
// ---------------------------------------------------------------------------
constexpr int AST = 36;

__global__ __launch_bounds__(256, 2) void attn_kernel() {
    const int qb = (int)gridDim.x - 1 - (int)blockIdx.x;
    const int h  = blockIdx.y;
    const int bh = blockIdx.z * H_ + h;

    const uint32_t* Qhg = q_hi + (size_t)bh * S_ * 32;
    const uint32_t* Qlg = q_lo + (size_t)bh * S_ * 32;
    const uint32_t* Khg = k_hi + (size_t)bh * S_ * 32;
    const uint32_t* Klg = k_lo + (size_t)bh * S_ * 32;
    const uint32_t* Vhg = v_hi + (size_t)bh * (HS_ * (S_ / 2));
    const uint32_t* Vlg = v_lo + (size_t)bh * (HS_ * (S_ / 2));

    const int tid  = threadIdx.x;
    const int warp = tid >> 5;
    const int lane = tid & 31;
    const int gid  = lane >> 2;
    const int tig  = lane & 3;
    const int wm   = warp * 16;

    __shared__ uint32_t Kh[64 * AST], Kl[64 * AST];
    __shared__ uint32_t Vh[64 * AST], Vl[64 * AST];
    const uint32_t sKh = (uint32_t)__cvta_generic_to_shared(Kh);
    const uint32_t sKl = (uint32_t)__cvta_generic_to_shared(Kl);
    const uint32_t sVh = (uint32_t)__cvta_generic_to_shared(Vh);
    const uint32_t sVl = (uint32_t)__cvta_generic_to_shared(Vl);

    // ldmatrix lane offset for B-style x4 over an nt-pair (rows = n, cols = k)
    const int r8 = lane & 7;
    const int lmoff = ((r8 + (lane >> 4) * 8) * AST + ((lane >> 3) & 1) * 4) * 4;

    const int rg = qb * 128 + wm + gid;
    uint32_t qh[4][4], ql[4][4];
    #pragma unroll
    for (int ks = 0; ks < 4; ks++) {
        int off = 8 * ks + tig;
        qh[ks][0] = Qhg[(size_t)rg * 32 + off];
        qh[ks][1] = Qhg[(size_t)(rg + 8) * 32 + off];
        qh[ks][2] = Qhg[(size_t)rg * 32 + off + 4];
        qh[ks][3] = Qhg[(size_t)(rg + 8) * 32 + off + 4];
        ql[ks][0] = Qlg[(size_t)rg * 32 + off];
        ql[ks][1] = Qlg[(size_t)(rg + 8) * 32 + off];
        ql[ks][2] = Qlg[(size_t)rg * 32 + off + 4];
        ql[ks][3] = Qlg[(size_t)(rg + 8) * 32 + off + 4];
    }

    float m0r = -1e30f, m1r = -1e30f, l0 = 0.f, l1 = 0.f;
    float o[8][4];
    #pragma unroll
    for (int nd = 0; nd < 8; nd++)
        #pragma unroll
        for (int e = 0; e < 4; e++) o[nd][e] = 0.f;

    const int nkt = 2 * qb + 2;

    auto issueK = [&](int kt) {
        #pragma unroll
        for (int i = 0; i < 4; i++) {
            int c   = i * 256 + tid;
            int pl  = c >> 9;
            int row = (c >> 3) & 63;
            int ch  = c & 7;
            uint32_t* sdst = (pl ? Kl : Kh) + row * AST + ch * 4;
            const uint32_t* gsrc = (pl ? Klg : Khg) + (size_t)(kt * 64 + row) * 32 + ch * 4;
            cp16(sdst, gsrc);
        }
        CP_COMMIT;
    };
    auto issueV = [&](int kt) {
        #pragma unroll
        for (int i = 0; i < 4; i++) {
            int c   = i * 256 + tid;
            int pl  = c >> 9;
            int row = (c >> 3) & 63;
            int ch  = c & 7;
            uint32_t* sdst = (pl ? Vl : Vh) + row * AST + ch * 4;
            const uint32_t* gsrc = (pl ? Vlg : Vhg) + (size_t)row * (S_ / 2) + kt * 32 + ch * 4;
            cp16(sdst, gsrc);
        }
        CP_COMMIT;
    };

    issueK(0);

    for (int kt = 0; kt < nkt; kt++) {
        CP_WAIT0;
        __syncthreads();
        issueV(kt);

        const bool active = (64 * kt) <= (rg + 8);
        float s[8][4];
        if (active) {
            #pragma unroll
            for (int nt = 0; nt < 8; nt++)
                #pragma unroll
                for (int e = 0; e < 4; e++) s[nt][e] = 0.f;

            #pragma unroll
            for (int ks = 0; ks < 4; ks++) {
                const uint32_t kc = (uint32_t)(ks * 8 * 4) + lmoff;
                #pragma unroll
                for (int np = 0; np < 4; np++) {
                    uint32_t base = (uint32_t)(np * 16 * AST * 4) + kc;
                    uint32_t bh2[2][2], bl2[2][2];
                    ldsm_x4(bh2[0][0], bh2[0][1], bh2[1][0], bh2[1][1], sKh + base);
                    ldsm_x4(bl2[0][0], bl2[0][1], bl2[1][0], bl2[1][1], sKl + base);
                    mma_bf16(s[2*np],   qh[ks], bh2[0]);
                    mma_bf16(s[2*np],   qh[ks], bl2[0]);
                    mma_bf16(s[2*np],   ql[ks], bh2[0]);
                    mma_bf16(s[2*np+1], qh[ks], bh2[1]);
                    mma_bf16(s[2*np+1], qh[ks], bl2[1]);
                    mma_bf16(s[2*np+1], ql[ks], bh2[1]);
                }
            }
            if (64 * kt + 63 > rg) {
                #pragma unroll
                for (int nt = 0; nt < 8; nt++) {
                    int c0 = 64 * kt + 8 * nt + 2 * tig;
                    if (c0 > rg)         s[nt][0] = -1e30f;
                    if (c0 + 1 > rg)     s[nt][1] = -1e30f;
                    if (c0 > rg + 8)     s[nt][2] = -1e30f;
                    if (c0 + 1 > rg + 8) s[nt][3] = -1e30f;
                }
            }
            float rm0 = -1e30f, rm1 = -1e30f;
            #pragma unroll
            for (int nt = 0; nt < 8; nt++) {
                rm0 = fmaxf(rm0, fmaxf(s[nt][0], s[nt][1]));
                rm1 = fmaxf(rm1, fmaxf(s[nt][2], s[nt][3]));
            }
            #pragma unroll
            for (int off = 1; off < 4; off <<= 1) {
                rm0 = fmaxf(rm0, __shfl_xor_sync(0xffffffffu, rm0, off));
                rm1 = fmaxf(rm1, __shfl_xor_sync(0xffffffffu, rm1, off));
            }
            float mn0 = fmaxf(m0r, rm0), mn1 = fmaxf(m1r, rm1);
            float c0 = __expf(m0r - mn0), c1 = __expf(m1r - mn1);
            m0r = mn0; m1r = mn1;
            float rs0 = 0.f, rs1 = 0.f;
            #pragma unroll
            for (int nt = 0; nt < 8; nt++) {
                s[nt][0] = __expf(s[nt][0] - mn0);
                s[nt][1] = __expf(s[nt][1] - mn0);
                s[nt][2] = __expf(s[nt][2] - mn1);
                s[nt][3] = __expf(s[nt][3] - mn1);
                rs0 += s[nt][0] + s[nt][1];
                rs1 += s[nt][2] + s[nt][3];
            }
            #pragma unroll
            for (int off = 1; off < 4; off <<= 1) {
                rs0 += __shfl_xor_sync(0xffffffffu, rs0, off);
                rs1 += __shfl_xor_sync(0xffffffffu, rs1, off);
            }
            l0 = l0 * c0 + rs0;
            l1 = l1 * c1 + rs1;
            #pragma unroll
            for (int nd = 0; nd < 8; nd++) {
                o[nd][0] *= c0; o[nd][1] *= c0;
                o[nd][2] *= c1; o[nd][3] *= c1;
            }
        }

        CP_WAIT0;
        __syncthreads();
        if (kt + 1 < nkt) issueK(kt + 1);

        if (active) {
            #pragma unroll
            for (int ks = 0; ks < 4; ks++) {
                uint32_t ph[4], pl2[4];
                {
                    const float* sa = s[2 * ks];
                    const float* sb2 = s[2 * ks + 1];
                    decomp2(sa[0], sa[1], ph[0], pl2[0]);
                    decomp2(sa[2], sa[3], ph[1], pl2[1]);
                    decomp2(sb2[0], sb2[1], ph[2], pl2[2]);
                    decomp2(sb2[2], sb2[3], ph[3], pl2[3]);
                }
                const uint32_t kc = (uint32_t)(ks * 8 * 4) + lmoff;
                #pragma unroll
                for (int np = 0; np < 4; np++) {
                    uint32_t base = (uint32_t)(np * 16 * AST * 4) + kc;
                    uint32_t bh2[2][2], bl2[2][2];
                    ldsm_x4(bh2[0][0], bh2[0][1], bh2[1][0], bh2[1][1], sVh + base);
                    ldsm_x4(bl2[0][0], bl2[0][1], bl2[1][0], bl2[1][1], sVl + base);
                    mma_bf16(o[2*np],   ph, bh2[0]);
                    mma_bf16(o[2*np],   ph, bl2[0]);
                    mma_bf16(o[2*np],   pl2, bh2[0]);
                    mma_bf16(o[2*np+1], ph, bh2[1]);
                    mma_bf16(o[2*np+1], ph, bl2[1]);
                    mma_bf16(o[2*np+1], pl2, bh2[1]);
                }
            }
        }
        __syncthreads();
    }

    float inv0 = 1.f / l0, inv1 = 1.f / l1;
    const int mglob = blockIdx.z * S_ + rg;
    #pragma unroll
    for (int nd = 0; nd < 8; nd++) {
        int kp = h * 32 + 4 * nd + tig;
        uint32_t hi, lo;
        decomp2(o[nd][0] * inv0, o[nd][1] * inv0, hi, lo);
        o_hi[(size_t)mglob * KP_ + kp] = hi;
        o_lo[(size_t)mglob * KP_ + kp] = lo;
        decomp2(o[nd][2] * inv1, o[nd][3] * inv1, hi, lo);
        o_hi[(size_t)(mglob + 8) * KP_ + kp] = hi;
        o_lo[(size_t)(mglob + 8) * KP_ + kp] = lo;
    }
}

// ---------------------------------------------------------------------------
extern "C" void kernel_launch(void* const* d_in, const int* in_sizes, int n_in,
                              void* d_out, int out_size) {
    const float* x  = (const float*)d_in[0];
    const float* Wq = (const float*)d_in[1];
    const float* Wk = (const float*)d_in[2];
    const float* Wv = (const float*)d_in[3];
    const float* Wp = (const float*)d_in[4];
    const float* bp = (const float*)d_in[5];
    float* out = (float*)d_out;

    cudaFuncSetAttribute(qkv_gemm, cudaFuncAttributeMaxDynamicSharedMemorySize, GEMM_SMEM);
    cudaFuncSetAttribute(proj_gemm, cudaFuncAttributeMaxDynamicSharedMemorySize, GEMM_SMEM);

    pack_x_kernel<<<(M_ * KP_) / 256, 256>>>(x);
    pack_w_kernel<<<(3 * C_ * KP_) / 256, 256>>>(Wq, Wk, Wv);
    pack_wp_kernel<<<(C_ * KP_) / 256, 256>>>(Wp);
    qkv_gemm<<<dim3(C_ / 128, M_ / 128, 3), 256, GEMM_SMEM>>>();
    pack_v_kernel<<<dim3(S_ / 128, B_ * H_), 256>>>();
    attn_kernel<<<dim3(S_ / 128, H_, B_), 256>>>();
    proj_gemm<<<dim3(C_ / 128, M_ / 128), 256, GEMM_SMEM>>>(bp, out);
}

// round 16
// speedup vs baseline: 1.0164x; 1.0164x over previous
#include <cuda_runtime.h>
#include <cuda_bf16.h>
#include <cstdint>

constexpr int B_  = 4;
constexpr int S_  = 2048;
constexpr int C_  = 1024;
constexpr int H_  = 16;
constexpr int HS_ = 64;
constexpr int M_  = B_ * S_;                    // 8192
constexpr int QKV_ELEMS = B_ * H_ * S_ * HS_;   // 8388608
constexpr int KP_ = C_ / 2;                     // 512 packed k-pairs

__device__ float g_v[QKV_ELEMS];                    // V fp32 [B,H,S,HS] (pack_v input)
__device__ uint32_t g_whi[3 * C_ * KP_];            // [mat][n][kp] packed bf16 pairs
__device__ uint32_t g_wlo[3 * C_ * KP_];
__device__ uint32_t g_phi[C_ * KP_];                // [n][kp] for Wp^T
__device__ uint32_t g_plo[C_ * KP_];

// activation hi/lo planes (packed bf16 pairs)
__device__ uint32_t x_hi[M_ * KP_];                 // [m][kp]
__device__ uint32_t x_lo[M_ * KP_];
__device__ uint32_t o_hi[M_ * KP_];                 // [m][kp], kp = h*32 + d/2
__device__ uint32_t o_lo[M_ * KP_];
__device__ uint32_t q_hi[QKV_ELEMS / 2];            // [bh][s][dp] (scaled 0.125)
__device__ uint32_t q_lo[QKV_ELEMS / 2];
__device__ uint32_t k_hi[QKV_ELEMS / 2];
__device__ uint32_t k_lo[QKV_ELEMS / 2];
__device__ uint32_t v_hi[QKV_ELEMS / 2];            // [bh][d][tp] (pairs over t)
__device__ uint32_t v_lo[QKV_ELEMS / 2];

// ---------------------------------------------------------------------------
__device__ __forceinline__ uint32_t pack2(__nv_bfloat16 a, __nv_bfloat16 b) {
    __nv_bfloat162 t; t.x = a; t.y = b;
    return *reinterpret_cast<uint32_t*>(&t);
}
__device__ __forceinline__ void decomp2(float a, float b, uint32_t& hi, uint32_t& lo) {
    __nv_bfloat16 ha = __float2bfloat16(a);
    __nv_bfloat16 hb = __float2bfloat16(b);
    __nv_bfloat16 la = __float2bfloat16(a - __bfloat162float(ha));
    __nv_bfloat16 lb = __float2bfloat16(b - __bfloat162float(hb));
    hi = pack2(ha, hb);
    lo = pack2(la, lb);
}

__device__ __forceinline__ void mma_bf16(float* d, const uint32_t* a, const uint32_t* b) {
    asm volatile(
        "mma.sync.aligned.m16n8k16.row.col.f32.bf16.bf16.f32 "
        "{%0,%1,%2,%3}, {%4,%5,%6,%7}, {%8,%9}, {%0,%1,%2,%3};\n"
        : "+f"(d[0]), "+f"(d[1]), "+f"(d[2]), "+f"(d[3])
        : "r"(a[0]), "r"(a[1]), "r"(a[2]), "r"(a[3]), "r"(b[0]), "r"(b[1]));
}

__device__ __forceinline__ void ldsm_x4(uint32_t& r0, uint32_t& r1,
                                        uint32_t& r2, uint32_t& r3, uint32_t saddr) {
    asm volatile("ldmatrix.sync.aligned.m8n8.x4.shared.b16 {%0,%1,%2,%3}, [%4];"
                 : "=r"(r0), "=r"(r1), "=r"(r2), "=r"(r3) : "r"(saddr));
}

__device__ __forceinline__ void cp16(void* dst, const void* src) {
    uint32_t d = (uint32_t)__cvta_generic_to_shared(dst);
    asm volatile("cp.async.cg.shared.global [%0], [%1], 16;" :: "r"(d), "l"(src));
}
// L1-caching variant: used for the A-activation planes, which are shared by
// the co-resident CTA and the bx-adjacent CTA (same m-tile).
__device__ __forceinline__ void cp16_ca(void* dst, const void* src) {
    uint32_t d = (uint32_t)__cvta_generic_to_shared(dst);
    asm volatile("cp.async.ca.shared.global [%0], [%1], 16;" :: "r"(d), "l"(src));
}
#define CP_COMMIT asm volatile("cp.async.commit_group;")
#define CP_WAIT0  asm volatile("cp.async.wait_group 0;")
#define CP_WAIT1  asm volatile("cp.async.wait_group 1;")

// ---------------------------------------------------------------------------
// Packs (512-thread blocks)
// ---------------------------------------------------------------------------
__global__ void pack_x_kernel(const float* __restrict__ x) {
    int idx = blockIdx.x * 512 + threadIdx.x;
    int m  = idx >> 9;
    int kp = idx & 511;
    float2 f = *(const float2*)(x + (size_t)m * C_ + 2 * kp);
    uint32_t hi, lo;
    decomp2(f.x, f.y, hi, lo);
    x_hi[idx] = hi;
    x_lo[idx] = lo;
}

__global__ void pack_w_kernel(const float* __restrict__ Wq,
                              const float* __restrict__ Wk,
                              const float* __restrict__ Wv) {
    int idx = blockIdx.x * 512 + threadIdx.x;
    int mat = idx / (C_ * KP_);
    int rem = idx - mat * (C_ * KP_);
    int n   = rem >> 9;
    int kp  = rem & 511;
    const float* W = (mat == 0) ? Wq : (mat == 1) ? Wk : Wv;
    int h = n >> 6, d = n & 63;
    const float* base = W + (size_t)h * C_ * HS_ + (size_t)(2 * kp) * HS_ + d;
    uint32_t hi, lo;
    decomp2(base[0], base[HS_], hi, lo);
    g_whi[idx] = hi;
    g_wlo[idx] = lo;
}

__global__ void pack_wp_kernel(const float* __restrict__ Wp) {
    int idx = blockIdx.x * 512 + threadIdx.x;
    int n  = idx >> 9;
    int kp = idx & 511;
    float2 f = *(const float2*)(Wp + (size_t)n * C_ + 2 * kp);
    uint32_t hi, lo;
    decomp2(f.x, f.y, hi, lo);
    g_phi[idx] = hi;
    g_plo[idx] = lo;
}

__global__ __launch_bounds__(256) void pack_v_kernel() {
    const int bh = blockIdx.y;
    const int t0 = blockIdx.x * 128;
    __shared__ float sm[128][65];
    const int tid = threadIdx.x;

    const float* src = g_v + (size_t)bh * S_ * HS_ + (size_t)t0 * HS_;
    #pragma unroll
    for (int i = 0; i < 8; i++) {
        int lin = i * 256 + tid;
        int row = lin >> 4, c4 = lin & 15;
        float4 v = *(const float4*)(src + (size_t)row * HS_ + c4 * 4);
        sm[row][c4 * 4 + 0] = v.x;
        sm[row][c4 * 4 + 1] = v.y;
        sm[row][c4 * 4 + 2] = v.z;
        sm[row][c4 * 4 + 3] = v.w;
    }
    __syncthreads();

    const size_t obase = (size_t)bh * (HS_ * (S_ / 2)) + (size_t)(t0 >> 1);
    #pragma unroll
    for (int j = 0; j < 16; j++) {
        int d  = (tid >> 6) + j * 4;
        int tp = tid & 63;
        uint32_t hi, lo;
        decomp2(sm[2 * tp][d], sm[2 * tp + 1][d], hi, lo);
        v_hi[obase + (size_t)d * (S_ / 2) + tp] = hi;
        v_lo[obase + (size_t)d * (S_ / 2) + tp] = lo;
    }
}

// ---------------------------------------------------------------------------
// GEMM: K-step 32 per stage, 2-stage double buffer, ldmatrix fragment loads.
// Stride 20 u32/row: ldmatrix 8-row phases hit banks {0,20,8,28,16,4,24,12}.
// ---------------------------------------------------------------------------
constexpr int PSTR = 20;
constexpr int STAGE_U32 = 4 * 128 * PSTR;           // 40960 B
constexpr int GEMM_SMEM = 2 * STAGE_U32 * 4;        // 81920 B

__device__ __forceinline__ void gemm_compute(
    uint32_t sAh, uint32_t sAl, uint32_t sBh, uint32_t sBl,   // smem byte addrs
    int wm, int wn, int lane, float acc[4][4][4])
{
    const int r8 = lane & 7;
    const int aoff = ((r8 + ((lane >> 3) & 1) * 8) * PSTR + (lane >> 4) * 4) * 4;
    const int boff = ((r8 + (lane >> 4) * 8) * PSTR + ((lane >> 3) & 1) * 4) * 4;

    #pragma unroll
    for (int ks = 0; ks < 2; ks++) {
        const int kc = ks * 8 * 4;
        uint32_t ah[4][4], al[4][4], bh[4][2], bl[4][2];
        #pragma unroll
        for (int mt = 0; mt < 4; mt++) {
            uint32_t base = (uint32_t)((wm + mt * 16) * PSTR * 4 + kc) + aoff;
            ldsm_x4(ah[mt][0], ah[mt][1], ah[mt][2], ah[mt][3], sAh + base);
            ldsm_x4(al[mt][0], al[mt][1], al[mt][2], al[mt][3], sAl + base);
        }
        #pragma unroll
        for (int np = 0; np < 2; np++) {
            uint32_t base = (uint32_t)((wn + np * 16) * PSTR * 4 + kc) + boff;
            ldsm_x4(bh[2*np][0], bh[2*np][1], bh[2*np+1][0], bh[2*np+1][1], sBh + base);
            ldsm_x4(bl[2*np][0], bl[2*np][1], bl[2*np+1][0], bl[2*np+1][1], sBl + base);
        }
        #pragma unroll
        for (int mt = 0; mt < 4; mt++)
            #pragma unroll
            for (int nt = 0; nt < 4; nt++) {
                mma_bf16(acc[mt][nt], ah[mt], bh[nt]);
                mma_bf16(acc[mt][nt], ah[mt], bl[nt]);
                mma_bf16(acc[mt][nt], al[mt], bh[nt]);
            }
    }
}

// Issue one K32 stage: A planes via .ca (L1-shared across CTAs), B via .cg.
__device__ __forceinline__ void gemm_issue(
    uint32_t* stage,
    const uint32_t* __restrict__ Ahg, const uint32_t* __restrict__ Alg,
    const uint32_t* __restrict__ Bhg, const uint32_t* __restrict__ Blg,
    int m0, int n0, int kp0, int tid)
{
    #pragma unroll
    for (int i = 0; i < 8; i++) {
        int c     = i * 256 + tid;
        int plane = c >> 9;                 // 0:Ah 1:Al 2:Bh 3:Bl
        int rem   = c & 511;
        int row   = rem >> 2;
        int ch    = rem & 3;
        uint32_t* dst = stage + plane * (128 * PSTR) + row * PSTR + ch * 4;
        if (plane < 2) {
            const uint32_t* srcb = plane ? Alg : Ahg;
            cp16_ca(dst, srcb + (size_t)(m0 + row) * KP_ + kp0 + ch * 4);
        } else {
            const uint32_t* srcb = (plane == 2) ? Bhg : Blg;
            cp16(dst, srcb + (size_t)(n0 + row) * KP_ + kp0 + ch * 4);
        }
    }
    CP_COMMIT;
}

// ---------------------------------------------------------------------------
// QKV GEMM (double-buffered). Epilogue: q/k packed planes (q scaled), v fp32.
// ---------------------------------------------------------------------------
__global__ __launch_bounds__(256, 2) void qkv_gemm() {
    const int mat = blockIdx.z;
    const uint32_t* Whi = g_whi + (size_t)mat * C_ * KP_;
    const uint32_t* Wlo = g_wlo + (size_t)mat * C_ * KP_;

    const int n0 = blockIdx.x * 128;
    const int m0 = blockIdx.y * 128;

    extern __shared__ uint32_t dynsm[];
    uint32_t* stg[2] = {dynsm, dynsm + STAGE_U32};
    const uint32_t sb = (uint32_t)__cvta_generic_to_shared(dynsm);

    const int tid  = threadIdx.x;
    const int warp = tid >> 5;
    const int lane = tid & 31;
    const int gid  = lane >> 2;
    const int tig  = lane & 3;
    const int wm   = (warp & 1) * 64;
    const int wn   = (warp >> 1) * 32;

    float acc[4][4][4];
    #pragma unroll
    for (int mt = 0; mt < 4; mt++)
        #pragma unroll
        for (int nt = 0; nt < 4; nt++)
            #pragma unroll
            for (int e = 0; e < 4; e++) acc[mt][nt][e] = 0.f;

    gemm_issue(stg[0], x_hi, x_lo, Whi, Wlo, m0, n0, 0, tid);

    int st = 0;
    for (int kp0 = 0; kp0 < KP_; kp0 += 16) {
        if (kp0 + 16 < KP_) {
            gemm_issue(stg[st ^ 1], x_hi, x_lo, Whi, Wlo, m0, n0, kp0 + 16, tid);
            CP_WAIT1;
        } else {
            CP_WAIT0;
        }
        __syncthreads();
        uint32_t ss = sb + (uint32_t)(st * STAGE_U32 * 4);
        gemm_compute(ss, ss + 128 * PSTR * 4,
                     ss + 2 * 128 * PSTR * 4, ss + 3 * 128 * PSTR * 4,
                     wm, wn, lane, acc);
        __syncthreads();
        st ^= 1;
    }

    if (mat == 2) {
        #pragma unroll
        for (int mt = 0; mt < 4; mt++) {
            int r  = m0 + wm + mt * 16 + gid;
            int b  = r >> 11;
            int s0 = r & 2047;
            #pragma unroll
            for (int nt = 0; nt < 4; nt++) {
                int n    = n0 + wn + nt * 8 + 2 * tig;
                int head = n >> 6;
                int d    = n & 63;
                float* p0 = g_v + ((size_t)(b * H_ + head) * S_ + s0) * HS_ + d;
                *(float2*)p0             = make_float2(acc[mt][nt][0], acc[mt][nt][1]);
                *(float2*)(p0 + 8 * HS_) = make_float2(acc[mt][nt][2], acc[mt][nt][3]);
            }
        }
    } else {
        const float scale = (mat == 0) ? 0.125f : 1.0f;
        uint32_t* hiP = (mat == 0) ? q_hi : k_hi;
        uint32_t* loP = (mat == 0) ? q_lo : k_lo;
        #pragma unroll
        for (int mt = 0; mt < 4; mt++) {
            int r  = m0 + wm + mt * 16 + gid;
            int b  = r >> 11;
            int s0 = r & 2047;
            #pragma unroll
            for (int nt = 0; nt < 4; nt++) {
                int n    = n0 + wn + nt * 8 + 2 * tig;
                int head = n >> 6;
                int dp   = (n & 63) >> 1;
                size_t i0 = ((size_t)(b * H_ + head) * S_ + s0) * 32 + dp;
                uint32_t hi, lo;
                decomp2(acc[mt][nt][0] * scale, acc[mt][nt][1] * scale, hi, lo);
                hiP[i0] = hi; loP[i0] = lo;
                decomp2(acc[mt][nt][2] * scale, acc[mt][nt][3] * scale, hi, lo);
                hiP[i0 + 8 * 32] = hi; loP[i0 + 8 * 32] = lo;
            }
        }
    }
}

// ---------------------------------------------------------------------------
// Projection GEMM (double-buffered): A = o planes, B = Wp^T planes.
// ---------------------------------------------------------------------------
__global__ __launch_bounds__(256, 2) void proj_gemm(
    const float* __restrict__ bp, float* __restrict__ out)
{
    const int n0 = blockIdx.x * 128;
    const int m0 = blockIdx.y * 128;

    extern __shared__ uint32_t dynsm[];
    uint32_t* stg[2] = {dynsm, dynsm + STAGE_U32};
    const uint32_t sb = (uint32_t)__cvta_generic_to_shared(dynsm);

    const int tid  = threadIdx.x;
    const int warp = tid >> 5;
    const int lane = tid & 31;
    const int gid  = lane >> 2;
    const int tig  = lane & 3;
    const int wm   = (warp & 1) * 64;
    const int wn   = (warp >> 1) * 32;

    float acc[4][4][4];
    #pragma unroll
    for (int mt = 0; mt < 4; mt++)
        #pragma unroll
        for (int nt = 0; nt < 4; nt++)
            #pragma unroll
            for (int e = 0; e < 4; e++) acc[mt][nt][e] = 0.f;

    gemm_issue(stg[0], o_hi, o_lo, g_phi, g_plo, m0, n0, 0, tid);

    int st = 0;
    for (int kp0 = 0; kp0 < KP_; kp0 += 16) {
        if (kp0 + 16 < KP_) {
            gemm_issue(stg[st ^ 1], o_hi, o_lo, g_phi, g_plo, m0, n0, kp0 + 16, tid);
            CP_WAIT1;
        } else {
            CP_WAIT0;
        }
        __syncthreads();
        uint32_t ss = sb + (uint32_t)(st * STAGE_U32 * 4);
        gemm_compute(ss, ss + 128 * PSTR * 4,
                     ss + 2 * 128 * PSTR * 4, ss + 3 * 128 * PSTR * 4,
                     wm, wn, lane, acc);
        __syncthreads();
        st ^= 1;
    }

    #pragma unroll
    for (int mt = 0; mt < 4; mt++) {
        int r = m0 + wm + mt * 16 + gid;
        #pragma unroll
        for (int nt = 0; nt < 4; nt++) {
            int n = n0 + wn + nt * 8 + 2 * tig;
            float2 bias = *(const float2*)(bp + n);
            *(float2*)(out + (size_t)r * C_ + n) =
                make_float2(acc[mt][nt][0] + bias.x, acc[mt][nt][1] + bias.y);
            *(float2*)(out + (size_t)(r + 8) * C_ + n) =
                make_float2(acc[mt][nt][2] + bias.x, acc[mt][nt][3] + bias.y);
        }
    }
}

// ---------------------------------------------------------------------------
// Flash attention (round-13, known good: mma.sync + ldmatrix + cp.async).
// ---------------------------------------------------------------------------
constexpr int AST = 36;

__global__ __launch_bounds__(256, 2) void attn_kernel() {
    const int qb = (int)gridDim.x - 1 - (int)blockIdx.x;
    const int h  = blockIdx.y;
    const int bh = blockIdx.z * H_ + h;

    const uint32_t* Qhg = q_hi + (size_t)bh * S_ * 32;
    const uint32_t* Qlg = q_lo + (size_t)bh * S_ * 32;
    const uint32_t* Khg = k_hi + (size_t)bh * S_ * 32;
    const uint32_t* Klg = k_lo + (size_t)bh * S_ * 32;
    const uint32_t* Vhg = v_hi + (size_t)bh * (HS_ * (S_ / 2));
    const uint32_t* Vlg = v_lo + (size_t)bh * (HS_ * (S_ / 2));

    const int tid  = threadIdx.x;
    const int warp = tid >> 5;
    const int lane = tid & 31;
    const int gid  = lane >> 2;
    const int tig  = lane & 3;
    const int wm   = warp * 16;

    __shared__ uint32_t Kh[64 * AST], Kl[64 * AST];
    __shared__ uint32_t Vh[64 * AST], Vl[64 * AST];
    const uint32_t sKh = (uint32_t)__cvta_generic_to_shared(Kh);
    const uint32_t sKl = (uint32_t)__cvta_generic_to_shared(Kl);
    const uint32_t sVh = (uint32_t)__cvta_generic_to_shared(Vh);
    const uint32_t sVl = (uint32_t)__cvta_generic_to_shared(Vl);

    const int r8 = lane & 7;
    const int lmoff = ((r8 + (lane >> 4) * 8) * AST + ((lane >> 3) & 1) * 4) * 4;

    const int rg = qb * 128 + wm + gid;
    uint32_t qh[4][4], ql[4][4];
    #pragma unroll
    for (int ks = 0; ks < 4; ks++) {
        int off = 8 * ks + tig;
        qh[ks][0] = Qhg[(size_t)rg * 32 + off];
        qh[ks][1] = Qhg[(size_t)(rg + 8) * 32 + off];
        qh[ks][2] = Qhg[(size_t)rg * 32 + off + 4];
        qh[ks][3] = Qhg[(size_t)(rg + 8) * 32 + off + 4];
        ql[ks][0] = Qlg[(size_t)rg * 32 + off];
        ql[ks][1] = Qlg[(size_t)(rg + 8) * 32 + off];
        ql[ks][2] = Qlg[(size_t)rg * 32 + off + 4];
        ql[ks][3] = Qlg[(size_t)(rg + 8) * 32 + off + 4];
    }

    float m0r = -1e30f, m1r = -1e30f, l0 = 0.f, l1 = 0.f;
    float o[8][4];
    #pragma unroll
    for (int nd = 0; nd < 8; nd++)
        #pragma unroll
        for (int e = 0; e < 4; e++) o[nd][e] = 0.f;

    const int nkt = 2 * qb + 2;

    auto issueK = [&](int kt) {
        #pragma unroll
        for (int i = 0; i < 4; i++) {
            int c   = i * 256 + tid;
            int pl  = c >> 9;
            int row = (c >> 3) & 63;
            int ch  = c & 7;
            uint32_t* sdst = (pl ? Kl : Kh) + row * AST + ch * 4;
            const uint32_t* gsrc = (pl ? Klg : Khg) + (size_t)(kt * 64 + row) * 32 + ch * 4;
            cp16(sdst, gsrc);
        }
        CP_COMMIT;
    };
    auto issueV = [&](int kt) {
        #pragma unroll
        for (int i = 0; i < 4; i++) {
            int c   = i * 256 + tid;
            int pl  = c >> 9;
            int row = (c >> 3) & 63;
            int ch  = c & 7;
            uint32_t* sdst = (pl ? Vl : Vh) + row * AST + ch * 4;
            const uint32_t* gsrc = (pl ? Vlg : Vhg) + (size_t)row * (S_ / 2) + kt * 32 + ch * 4;
            cp16(sdst, gsrc);
        }
        CP_COMMIT;
    };

    issueK(0);

    for (int kt = 0; kt < nkt; kt++) {
        CP_WAIT0;
        __syncthreads();
        issueV(kt);

        const bool active = (64 * kt) <= (rg + 8);
        float s[8][4];
        if (active) {
            #pragma unroll
            for (int nt = 0; nt < 8; nt++)
                #pragma unroll
                for (int e = 0; e < 4; e++) s[nt][e] = 0.f;

            #pragma unroll
            for (int ks = 0; ks < 4; ks++) {
                const uint32_t kc = (uint32_t)(ks * 8 * 4) + lmoff;
                #pragma unroll
                for (int np = 0; np < 4; np++) {
                    uint32_t base = (uint32_t)(np * 16 * AST * 4) + kc;
                    uint32_t bh2[2][2], bl2[2][2];
                    ldsm_x4(bh2[0][0], bh2[0][1], bh2[1][0], bh2[1][1], sKh + base);
                    ldsm_x4(bl2[0][0], bl2[0][1], bl2[1][0], bl2[1][1], sKl + base);
                    mma_bf16(s[2*np],   qh[ks], bh2[0]);
                    mma_bf16(s[2*np],   qh[ks], bl2[0]);
                    mma_bf16(s[2*np],   ql[ks], bh2[0]);
                    mma_bf16(s[2*np+1], qh[ks], bh2[1]);
                    mma_bf16(s[2*np+1], qh[ks], bl2[1]);
                    mma_bf16(s[2*np+1], ql[ks], bh2[1]);
                }
            }
            if (64 * kt + 63 > rg) {
                #pragma unroll
                for (int nt = 0; nt < 8; nt++) {
                    int c0 = 64 * kt + 8 * nt + 2 * tig;
                    if (c0 > rg)         s[nt][0] = -1e30f;
                    if (c0 + 1 > rg)     s[nt][1] = -1e30f;
                    if (c0 > rg + 8)     s[nt][2] = -1e30f;
                    if (c0 + 1 > rg + 8) s[nt][3] = -1e30f;
                }
            }
            float rm0 = -1e30f, rm1 = -1e30f;
            #pragma unroll
            for (int nt = 0; nt < 8; nt++) {
                rm0 = fmaxf(rm0, fmaxf(s[nt][0], s[nt][1]));
                rm1 = fmaxf(rm1, fmaxf(s[nt][2], s[nt][3]));
            }
            #pragma unroll
            for (int off = 1; off < 4; off <<= 1) {
                rm0 = fmaxf(rm0, __shfl_xor_sync(0xffffffffu, rm0, off));
                rm1 = fmaxf(rm1, __shfl_xor_sync(0xffffffffu, rm1, off));
            }
            float mn0 = fmaxf(m0r, rm0), mn1 = fmaxf(m1r, rm1);
            float c0 = __expf(m0r - mn0), c1 = __expf(m1r - mn1);
            m0r = mn0; m1r = mn1;
            float rs0 = 0.f, rs1 = 0.f;
            #pragma unroll
            for (int nt = 0; nt < 8; nt++) {
                s[nt][0] = __expf(s[nt][0] - mn0);
                s[nt][1] = __expf(s[nt][1] - mn0);
                s[nt][2] = __expf(s[nt][2] - mn1);
                s[nt][3] = __expf(s[nt][3] - mn1);
                rs0 += s[nt][0] + s[nt][1];
                rs1 += s[nt][2] + s[nt][3];
            }
            #pragma unroll
            for (int off = 1; off < 4; off <<= 1) {
                rs0 += __shfl_xor_sync(0xffffffffu, rs0, off);
                rs1 += __shfl_xor_sync(0xffffffffu, rs1, off);
            }
            l0 = l0 * c0 + rs0;
            l1 = l1 * c1 + rs1;
            #pragma unroll
            for (int nd = 0; nd < 8; nd++) {
                o[nd][0] *= c0; o[nd][1] *= c0;
                o[nd][2] *= c1; o[nd][3] *= c1;
            }
        }

        CP_WAIT0;
        __syncthreads();
        if (kt + 1 < nkt) issueK(kt + 1);

        if (active) {
            #pragma unroll
            for (int ks = 0; ks < 4; ks++) {
                uint32_t ph[4], pl2[4];
                {
                    const float* sa = s[2 * ks];
                    const float* sb2 = s[2 * ks + 1];
                    decomp2(sa[0], sa[1], ph[0], pl2[0]);
                    decomp2(sa[2], sa[3], ph[1], pl2[1]);
                    decomp2(sb2[0], sb2[1], ph[2], pl2[2]);
                    decomp2(sb2[2], sb2[3], ph[3], pl2[3]);
                }
                const uint32_t kc = (uint32_t)(ks * 8 * 4) + lmoff;
                #pragma unroll
                for (int np = 0; np < 4; np++) {
                    uint32_t base = (uint32_t)(np * 16 * AST * 4) + kc;
                    uint32_t bh2[2][2], bl2[2][2];
                    ldsm_x4(bh2[0][0], bh2[0][1], bh2[1][0], bh2[1][1], sVh + base);
                    ldsm_x4(bl2[0][0], bl2[0][1], bl2[1][0], bl2[1][1], sVl + base);
                    mma_bf16(o[2*np],   ph, bh2[0]);
                    mma_bf16(o[2*np],   ph, bl2[0]);
                    mma_bf16(o[2*np],   pl2, bh2[0]);
                    mma_bf16(o[2*np+1], ph, bh2[1]);
                    mma_bf16(o[2*np+1], ph, bl2[1]);
                    mma_bf16(o[2*np+1], pl2, bh2[1]);
                }
            }
        }
        __syncthreads();
    }

    float inv0 = 1.f / l0, inv1 = 1.f / l1;
    const int mglob = blockIdx.z * S_ + rg;
    #pragma unroll
    for (int nd = 0; nd < 8; nd++) {
        int kp = h * 32 + 4 * nd + tig;
        uint32_t hi, lo;
        decomp2(o[nd][0] * inv0, o[nd][1] * inv0, hi, lo);
        o_hi[(size_t)mglob * KP_ + kp] = hi;
        o_lo[(size_t)mglob * KP_ + kp] = lo;
        decomp2(o[nd][2] * inv1, o[nd][3] * inv1, hi, lo);
        o_hi[(size_t)(mglob + 8) * KP_ + kp] = hi;
        o_lo[(size_t)(mglob + 8) * KP_ + kp] = lo;
    }
}

// ---------------------------------------------------------------------------
extern "C" void kernel_launch(void* const* d_in, const int* in_sizes, int n_in,
                              void* d_out, int out_size) {
    const float* x  = (const float*)d_in[0];
    const float* Wq = (const float*)d_in[1];
    const float* Wk = (const float*)d_in[2];
    const float* Wv = (const float*)d_in[3];
    const float* Wp = (const float*)d_in[4];
    const float* bp = (const float*)d_in[5];
    float* out = (float*)d_out;

    cudaFuncSetAttribute(qkv_gemm, cudaFuncAttributeMaxDynamicSharedMemorySize, GEMM_SMEM);
    cudaFuncSetAttribute(proj_gemm, cudaFuncAttributeMaxDynamicSharedMemorySize, GEMM_SMEM);

    pack_x_kernel<<<(M_ * KP_) / 512, 512>>>(x);
    pack_w_kernel<<<(3 * C_ * KP_) / 512, 512>>>(Wq, Wk, Wv);
    pack_wp_kernel<<<(C_ * KP_) / 512, 512>>>(Wp);
    qkv_gemm<<<dim3(C_ / 128, M_ / 128, 3), 256, GEMM_SMEM>>>();
    pack_v_kernel<<<dim3(S_ / 128, B_ * H_), 256>>>();
    attn_kernel<<<dim3(S_ / 128, H_, B_), 256>>>();
    proj_gemm<<<dim3(C_ / 128, M_ / 128), 256, GEMM_SMEM>>>(bp, out);
}